// round 16
// baseline (speedup 1.0000x reference)
#include <cuda_runtime.h>
#include <cuda_fp16.h>
#include <mma.h>
#include <cstdint>

using namespace nvcuda;

#define NN 8192
#define CC 256

// ---------------------------------------------------------------------------
// Scratch (__device__ globals; allocation-free rule)
// ---------------------------------------------------------------------------
__device__ float  g_s[NN];                       // d^{-1/2} (producer-written)
__device__ __half g_adjh[(size_t)NN * NN];       // fp16(adj[i][j] * s_j)
__device__ __half g_xh[NN * CC];                 // fp16(x)   [K][N]
__device__ __half g_a2h[NN * CC];                // fp16(s_i*(t + s_i*x)) [M][K]
__device__ __half g_wh[CC * CC];                 // fp16(w)   [K][N]
__device__ int    g_pflag[128];                  // per-K-panel ready flag

// ---------------------------------------------------------------------------
__device__ __forceinline__ uint32_t smem_u32(const void* p) {
    uint32_t a;
    asm("{ .reg .u64 t; cvta.to.shared.u64 t, %1; cvt.u32.u64 %0, t; }" : "=r"(a) : "l"(p));
    return a;
}
__device__ __forceinline__ void cpa16(uint32_t s, const void* g) {
    asm volatile("cp.async.cg.shared.global [%0], [%1], 16;" :: "r"(s), "l"(g));
}
#define CP_COMMIT() asm volatile("cp.async.commit_group;" ::: "memory")
#define CP_WAIT_2() asm volatile("cp.async.wait_group 2;" ::: "memory")
#define CP_WAIT_0() asm volatile("cp.async.wait_group 0;" ::: "memory")

// ---------------------------------------------------------------------------
// prep (trivial now): xh = fp16(x), wh = fp16(w), reset flags.
// blocks 0..2047: x. blocks 2048..2111: w. block 2112: flags.
// ---------------------------------------------------------------------------
__global__ void prep_kernel(const float* __restrict__ x,
                            const float* __restrict__ w) {
    const int b = blockIdx.x, t = threadIdx.x;
    if (b == 2112) {
        if (t < 128) g_pflag[t] = 0;
        return;
    }
    if (b >= 2048) {
        const int idx = (b - 2048) * 256 + t;   // CC*CC/4 = 16384 float4
        float4 v = reinterpret_cast<const float4*>(w)[idx];
        __half2 h0 = __floats2half2_rn(v.x, v.y);
        __half2 h1 = __floats2half2_rn(v.z, v.w);
        uint2 u;
        u.x = *reinterpret_cast<uint32_t*>(&h0);
        u.y = *reinterpret_cast<uint32_t*>(&h1);
        reinterpret_cast<uint2*>(g_wh)[idx] = u;
        return;
    }
    const int idx = b * 256 + t;                // NN*CC/4 = 524288 float4
    float4 v = reinterpret_cast<const float4*>(x)[idx];
    __half2 h0 = __floats2half2_rn(v.x, v.y);
    __half2 h1 = __floats2half2_rn(v.z, v.w);
    uint2 u;
    u.x = *reinterpret_cast<uint32_t*>(&h0);
    u.y = *reinterpret_cast<uint32_t*>(&h1);
    reinterpret_cast<uint2*>(g_xh)[idx] = u;
}

// ---------------------------------------------------------------------------
// GEMM tiling (champion): 128x128 tile, BK=64, 4-stage, reg-dbuf, f32 acc.
// ---------------------------------------------------------------------------
constexpr int BM = 128, BN = 128, BK = 64, STAGES = 4;
constexpr int APAD = 72;
constexpr int BPAD = 136;
constexpr int A_HALVES = BM * APAD;        // 9216
constexpr int B_HALVES = BK * BPAD;        // 8704
constexpr int STAGE_BYTES = (A_HALVES + B_HALVES) * 2;   // 35840
constexpr int SMEM1_BYTES = STAGES * STAGE_BYTES;         // 143360
constexpr int NPROD = 20;                  // producer CTAs (idle SMs)

// ---------------------------------------------------------------------------
// Fused kernel: cid<128 -> gemm consumer tile; cid>=128 -> panel producer.
// Producers: for each owned panel kt: rowsum rows kt*64..+63 -> s; then
// convert adj[:, kt*64..+64) * s_j -> adjh; fence; flag. Never wait.
// Consumers: champion gemm1 with flag-gated stage loads.
// ---------------------------------------------------------------------------
__global__ __launch_bounds__(256, 1)
void gcn_fused1(const float* __restrict__ adj, const float* __restrict__ xin) {
    extern __shared__ char smem[];
    const int cid = blockIdx.x;
    const int tid = threadIdx.x;

    if (cid >= 128) {
        // ================= PRODUCER =================
        const int p = cid - 128;
        const int warp = tid >> 5, lane = tid & 31;
        float* ss = reinterpret_cast<float*>(smem);   // 64 s values

        for (int panel = p; panel < 128; panel += NPROD) {
            // 1) rowsum for this panel's 64 j-rows -> s_j
            for (int rr = warp; rr < 64; rr += 8) {
                const int row = panel * 64 + rr;
                const float4* pr = reinterpret_cast<const float4*>(adj + (size_t)row * NN);
                float sum = 0.0f;
#pragma unroll 8
                for (int i = lane; i < NN / 4; i += 32) {
                    float4 v = __ldcs(pr + i);
                    sum += (v.x + v.y) + (v.z + v.w);
                }
#pragma unroll
                for (int o = 16; o > 0; o >>= 1) sum += __shfl_xor_sync(0xffffffffu, sum, o);
                if (lane == 0) {
                    const float s = rsqrtf(sum + 1.0f);
                    g_s[row] = s;
                    ss[rr] = s;
                }
            }
            __syncthreads();

            // 2) convert slab: adjh[row][panel*64 + c] = fp16(adj * s_col)
            // flat f = tid + 256*i : row = f>>4 (8192), c4 = f&15 (16 float4/row)
            const float4 s4a = *reinterpret_cast<const float4*>(ss + ((tid & 15) * 4));
#pragma unroll 4
            for (int i = 0; i < 512; i++) {
                const int f = tid + (i << 8);
                const int row = f >> 4, c4 = f & 15;
                const float4 v = __ldcs(
                    reinterpret_cast<const float4*>(adj + (size_t)row * NN + panel * 64) + c4);
                __half2 h0 = __floats2half2_rn(v.x * s4a.x, v.y * s4a.y);
                __half2 h1 = __floats2half2_rn(v.z * s4a.z, v.w * s4a.w);
                uint2 u;
                u.x = *reinterpret_cast<uint32_t*>(&h0);
                u.y = *reinterpret_cast<uint32_t*>(&h1);
                *reinterpret_cast<uint2*>(g_adjh + (size_t)row * NN + panel * 64 + c4 * 4) = u;
            }
            __threadfence();
            __syncthreads();
            if (tid == 0) atomicExch(&g_pflag[panel], 1);
            __syncthreads();
        }
        return;
    }

    // ================= CONSUMER (gemm1) =================
    const uint32_t sb = smem_u32(smem);
    const int warp = tid >> 5;
    const int wm = warp & 3;     // 0..3 along M
    const int wn = warp >> 2;    // 0..1 along N
    const int m0 = (cid >> 1) * BM;
    const int n0 = (cid & 1) * BN;

    const int arr = tid >> 3, arc = (tid & 7) * 8;
    const int brr = tid >> 4, brc = (tid & 15) * 8;
    const __half* gA = g_adjh + (size_t)(m0 + arr) * NN + arc;
    const __half* gB = g_xh + (size_t)brr * CC + n0 + brc;
    const uint32_t sAo = (arr * APAD + arc) * 2;
    const uint32_t sBo = A_HALVES * 2 + (brr * BPAD + brc) * 2;

    wmma::fragment<wmma::accumulator, 16, 16, 16, float> acc[2][4];
#pragma unroll
    for (int i = 0; i < 2; i++)
#pragma unroll
        for (int j = 0; j < 4; j++) wmma::fill_fragment(acc[i][j], 0.0f);

    auto wait_panel = [&](int pn) {
        if (tid == 0) {
            while (reinterpret_cast<volatile int*>(g_pflag)[pn] == 0) __nanosleep(64);
        }
        __syncthreads();
    };
    auto load_stage = [&](int kt, int s) {
        const uint32_t st = sb + s * STAGE_BYTES;
        const __half* a = gA + kt * BK;
        const __half* b = gB + (size_t)kt * BK * CC;
#pragma unroll
        for (int r = 0; r < 4; r++)
            cpa16(st + sAo + r * (32 * APAD * 2), a + (size_t)(r * 32) * NN);
#pragma unroll
        for (int r = 0; r < 4; r++)
            cpa16(st + sBo + r * (16 * BPAD * 2), b + (size_t)(r * 16) * CC);
    };

#pragma unroll
    for (int s = 0; s < STAGES - 1; s++) {
        wait_panel(s);
        load_stage(s, s);
        CP_COMMIT();
    }

    const int k_iters = NN / BK;   // 128
    for (int kt = 0; kt < k_iters; kt++) {
        CP_WAIT_2();
        __syncthreads();

        const int nk = kt + STAGES - 1;
        if (nk < k_iters) {
            wait_panel(nk);
            load_stage(nk, nk & 3);
        }
        CP_COMMIT();

        const __half* Ap = reinterpret_cast<const __half*>(smem + (kt & 3) * STAGE_BYTES);
        const __half* Bp = Ap + A_HALVES;

        wmma::fragment<wmma::matrix_a, 16, 16, 16, __half, wmma::row_major> af[2][2];
        wmma::fragment<wmma::matrix_b, 16, 16, 16, __half, wmma::row_major> bf[2][4];
#pragma unroll
        for (int i = 0; i < 2; i++)
            wmma::load_matrix_sync(af[0][i], Ap + (wm * 32 + i * 16) * APAD, APAD);
#pragma unroll
        for (int j = 0; j < 4; j++)
            wmma::load_matrix_sync(bf[0][j], Bp + wn * 64 + j * 16, BPAD);

#pragma unroll
        for (int ks = 0; ks < 4; ks++) {
            const int cu = ks & 1, nx = cu ^ 1;
            if (ks < 3) {
#pragma unroll
                for (int i = 0; i < 2; i++)
                    wmma::load_matrix_sync(af[nx][i],
                        Ap + (wm * 32 + i * 16) * APAD + (ks + 1) * 16, APAD);
#pragma unroll
                for (int j = 0; j < 4; j++)
                    wmma::load_matrix_sync(bf[nx][j],
                        Bp + ((ks + 1) * 16) * BPAD + wn * 64 + j * 16, BPAD);
            }
#pragma unroll
            for (int i = 0; i < 2; i++)
#pragma unroll
                for (int j = 0; j < 4; j++)
                    wmma::mma_sync(acc[i][j], af[cu][i], bf[cu][j], acc[i][j]);
        }
    }
    __syncthreads();

    // epilogue: a2h = fp16( s_i * (t + s_i * x) )  (all s ready: flag[127] seen)
    float* stg = reinterpret_cast<float*>(smem);   // 128 x 132
#pragma unroll
    for (int i = 0; i < 2; i++)
#pragma unroll
        for (int j = 0; j < 4; j++)
            wmma::store_matrix_sync(stg + (wm * 32 + i * 16) * 132 + wn * 64 + j * 16,
                                    acc[i][j], 132, wmma::mem_row_major);
    __syncthreads();

    const int r = tid >> 1;
    const int c0 = (tid & 1) * 64;
    const int grow = m0 + r;
    const float sA = g_s[grow];
#pragma unroll
    for (int c = 0; c < 64; c += 4) {
        float4 v = *reinterpret_cast<const float4*>(stg + r * 132 + c0 + c);
        const int gcol = n0 + c0 + c;
        const float4 xv = *reinterpret_cast<const float4*>(xin + (size_t)grow * CC + gcol);
        __half2 h0 = __floats2half2_rn(sA * (v.x + sA * xv.x), sA * (v.y + sA * xv.y));
        __half2 h1 = __floats2half2_rn(sA * (v.z + sA * xv.z), sA * (v.w + sA * xv.w));
        uint2 u;
        u.x = *reinterpret_cast<uint32_t*>(&h0);
        u.y = *reinterpret_cast<uint32_t*>(&h1);
        *reinterpret_cast<uint2*>(&g_a2h[(size_t)grow * CC + gcol]) = u;
    }
}

// ---------------------------------------------------------------------------
// gemm2 single-shot: out = ELU( a2h @ wh ).  Tile 64x128, grid (2,128).
// ---------------------------------------------------------------------------
constexpr int AP2 = 264;
constexpr int BP2 = 136;
constexpr int A2_HALVES = 64 * AP2;              // 16896
constexpr int SMEM2_BYTES = (A2_HALVES + 256 * BP2) * 2;   // 103424

__global__ __launch_bounds__(256, 1)
void gemm2_kernel(float* __restrict__ outp) {
    extern __shared__ char smem[];
    const uint32_t sb = smem_u32(smem);
    const int tid = threadIdx.x;
    const int warp = tid >> 5;
    const int wm = warp & 1;
    const int wn = warp >> 1;
    const int m0 = blockIdx.y * 64;
    const int n0 = blockIdx.x * 128;

    const __half* gA = g_a2h + (size_t)m0 * CC;
    const __half* gB = g_wh + n0;
#pragma unroll
    for (int r = 0; r < 8; r++) {
        const int c = tid + r * 256;
        const int row = c >> 5, col = (c & 31) * 8;
        cpa16(sb + (row * AP2 + col) * 2, gA + (size_t)row * CC + col);
        if ((r & 1) == 1) CP_COMMIT();
    }
#pragma unroll
    for (int r = 0; r < 16; r++) {
        const int c = tid + r * 256;
        const int row = c >> 4, col = (c & 15) * 8;
        cpa16(sb + A2_HALVES * 2 + (row * BP2 + col) * 2, gB + (size_t)row * CC + col);
        if ((r & 3) == 3) CP_COMMIT();
    }
    CP_WAIT_0();
    __syncthreads();

    const __half* Ap = reinterpret_cast<const __half*>(smem);
    const __half* Bp = Ap + A2_HALVES;

    wmma::fragment<wmma::accumulator, 16, 16, 16, float> acc[2][2];
#pragma unroll
    for (int i = 0; i < 2; i++)
#pragma unroll
        for (int j = 0; j < 2; j++) wmma::fill_fragment(acc[i][j], 0.0f);

    wmma::fragment<wmma::matrix_a, 16, 16, 16, __half, wmma::row_major> af[2][2];
    wmma::fragment<wmma::matrix_b, 16, 16, 16, __half, wmma::row_major> bf[2][2];
#pragma unroll
    for (int i = 0; i < 2; i++)
        wmma::load_matrix_sync(af[0][i], Ap + (wm * 32 + i * 16) * AP2, AP2);
#pragma unroll
    for (int j = 0; j < 2; j++)
        wmma::load_matrix_sync(bf[0][j], Bp + wn * 32 + j * 16, BP2);

#pragma unroll
    for (int ks = 0; ks < 16; ks++) {
        const int cu = ks & 1, nx = cu ^ 1;
        if (ks < 15) {
#pragma unroll
            for (int i = 0; i < 2; i++)
                wmma::load_matrix_sync(af[nx][i],
                    Ap + (wm * 32 + i * 16) * AP2 + (ks + 1) * 16, AP2);
#pragma unroll
            for (int j = 0; j < 2; j++)
                wmma::load_matrix_sync(bf[nx][j],
                    Bp + ((ks + 1) * 16) * BP2 + wn * 32 + j * 16, BP2);
        }
#pragma unroll
        for (int i = 0; i < 2; i++)
#pragma unroll
            for (int j = 0; j < 2; j++)
                wmma::mma_sync(acc[i][j], af[cu][i], bf[cu][j], acc[i][j]);
    }

#pragma unroll
    for (int i = 0; i < 2; i++)
#pragma unroll
        for (int j = 0; j < 2; j++) {
#pragma unroll
            for (int e = 0; e < 8; e++) {
                float v = acc[i][j].x[e];
                acc[i][j].x[e] = (v > 0.0f) ? v : expm1f(v);
            }
            const int r = m0 + wm * 32 + i * 16;
            const int c = n0 + wn * 32 + j * 16;
            wmma::store_matrix_sync(&outp[(size_t)r * CC + c], acc[i][j], CC,
                                    wmma::mem_row_major);
        }
}

// ---------------------------------------------------------------------------
extern "C" void kernel_launch(void* const* d_in, const int* in_sizes, int n_in,
                              void* d_out, int out_size) {
    const float *x = nullptr, *adj = nullptr, *w = nullptr;
    for (int i = 0; i < n_in; i++) {
        if (in_sizes[i] == NN * NN) adj = (const float*)d_in[i];
        else if (in_sizes[i] == NN * CC) x = (const float*)d_in[i];
        else if (in_sizes[i] == CC * CC) w = (const float*)d_in[i];
    }
    float* out = (float*)d_out;

    cudaFuncSetAttribute(gcn_fused1, cudaFuncAttributeMaxDynamicSharedMemorySize, SMEM1_BYTES);
    cudaFuncSetAttribute(gemm2_kernel, cudaFuncAttributeMaxDynamicSharedMemorySize, SMEM2_BYTES);

    // trivial prep: xh, wh, flag reset (~3 us)
    prep_kernel<<<2113, 256>>>(x, w);
    // fused: 128 gemm consumers + 20 streaming producers, 148 CTAs = 148 SMs,
    // all wave-1 resident (143KB smem forces 1 CTA/SM). Producers never wait.
    gcn_fused1<<<148, 256, SMEM1_BYTES>>>(adj, x);
    gemm2_kernel<<<dim3(2, 128), 256, SMEM2_BYTES>>>(out);
}